// round 4
// baseline (speedup 1.0000x reference)
#include <cuda_runtime.h>
#include <cuda_fp16.h>
#include <mma.h>

using namespace nvcuda;

#define NTOK 4096
#define DIM  2048
#define FFN  5632
#define NE   8
#define CAP  4096
// Compacted h rows: sum over experts of round_up(Te,128); worst case 8192 + 8*128
#define HROWS 9216

// Scratch (static __device__ globals — the sanctioned no-alloc scratch path)
__device__ __half g_h[(size_t)HROWS * FFN];  // compacted hidden activations, fp16 (104 MB)
__device__ int    g_tok[NE * CAP];
__device__ float  g_wt[NE * CAP];
__device__ int    g_cnt[NE];
__device__ int    g_off[NE];                 // 128-aligned row offset of expert e in g_h

__global__ void k_zero() {
  if (threadIdx.x < NE) g_cnt[threadIdx.x] = 0;
}

// Router: one warp per token (fp32 exact). top-2 + softmax, append to expert lists.
__global__ void __launch_bounds__(256) k_router(const float* __restrict__ x,
                                                const float* __restrict__ gw) {
  const int wid  = threadIdx.x >> 5;
  const int lane = threadIdx.x & 31;
  const int t = blockIdx.x * 8 + wid;

  float s[NE];
#pragma unroll
  for (int e = 0; e < NE; e++) s[e] = 0.f;

  const float* xr = x + (size_t)t * DIM;
  for (int i = lane; i < DIM; i += 32) {
    float xv = xr[i];
#pragma unroll
    for (int e = 0; e < NE; e++) s[e] += xv * gw[e * DIM + i];
  }
#pragma unroll
  for (int e = 0; e < NE; e++) {
#pragma unroll
    for (int o = 16; o; o >>= 1) s[e] += __shfl_down_sync(0xffffffffu, s[e], o);
  }

  if (lane == 0) {
    int e0 = 0; float v0 = s[0];
#pragma unroll
    for (int e = 1; e < NE; e++) if (s[e] > v0) { v0 = s[e]; e0 = e; }
    int e1 = -1; float v1 = -3.4e38f;
#pragma unroll
    for (int e = 0; e < NE; e++) if (e != e0 && s[e] > v1) { v1 = s[e]; e1 = e; }
    float ex = expf(v1 - v0);
    float w1 = ex / (1.f + ex);
    float w0 = 1.f - w1;
    int p0 = atomicAdd(&g_cnt[e0], 1);
    g_tok[e0 * CAP + p0] = t; g_wt[e0 * CAP + p0] = w0;
    int p1 = atomicAdd(&g_cnt[e1], 1);
    g_tok[e1 * CAP + p1] = t; g_wt[e1 * CAP + p1] = w1;
  }
}

// 128-row-aligned exclusive prefix over counts -> g_off
__global__ void k_offsets() {
  if (threadIdx.x == 0) {
    int acc = 0;
    for (int e = 0; e < NE; e++) {
      g_off[e] = acc;
      acc += (g_cnt[e] + 127) & ~127;
    }
  }
}

__global__ void __launch_bounds__(256) k_bias(float* __restrict__ out,
                                              const float* __restrict__ bias) {
  int i = blockIdx.x * blockDim.x + threadIdx.x;
  if (i < NTOK * DIM) out[i] = bias[i & (DIM - 1)];
}

// smem strides (in halves / floats) keeping all WMMA fragment bases 32B-aligned
#define SH 48   // half stride: 96 B = 3*32
#define SF 64   // float stride for epilogue staging: 256 B

// ---------------------------------------------------------------------------
// GEMM 1+2 fused (fp16 WMMA m16n16k16, fp32 accum):
//   g = X Wg^T, u = X Wu^T, h = silu(g)*u -> g_h (fp16, compacted)
// BM=128, BN=64, BK=32. 256 threads, 8 warps (4x2), warp tile 32x32.
// ---------------------------------------------------------------------------
__global__ void __launch_bounds__(256) k_gateup(const float* __restrict__ x,
                                                const float* __restrict__ wg,
                                                const float* __restrict__ wu) {
  const int e  = blockIdx.z;
  const int Te = g_cnt[e];
  const int m0 = blockIdx.x * 128;
  if (m0 >= Te) return;
  const int n0 = blockIdx.y * 64;

  __shared__ __align__(32) char smem[32768];
  __half* sA  = (__half*)smem;                  // 128*48 halves = 12288 B
  __half* sBg = (__half*)(smem + 12288);        // 64*48 = 6144 B
  __half* sBu = (__half*)(smem + 18432);        // 64*48 = 6144 B
  float*  fbuf = (float*)smem;                  // epilogue: 128*64 fp32 = 32768 B

  const int tid = threadIdx.x;
  const int wid = tid >> 5;
  const int wm = (wid >> 1) * 32;
  const int wn = (wid & 1) * 32;

  wmma::fragment<wmma::accumulator, 16, 16, 16, float> accg[2][2], accu[2][2];
#pragma unroll
  for (int i = 0; i < 2; i++)
#pragma unroll
    for (int j = 0; j < 2; j++) {
      wmma::fill_fragment(accg[i][j], 0.f);
      wmma::fill_fragment(accu[i][j], 0.f);
    }

  const int*   tokp = g_tok + e * CAP;
  const float* wgp  = wg + (size_t)e * FFN * DIM + (size_t)n0 * DIM;
  const float* wup  = wu + (size_t)e * FFN * DIM + (size_t)n0 * DIM;

  for (int k0 = 0; k0 < DIM; k0 += 32) {
    // sA: 128 rows x 8 float4-groups; convert fp32->fp16
#pragma unroll
    for (int v = 0; v < 4; v++) {
      int i = tid + v * 256;
      int r = i >> 3, c4 = i & 7;
      int slot = m0 + r;
      float4 val = make_float4(0.f, 0.f, 0.f, 0.f);
      if (slot < Te)
        val = *(const float4*)(x + (size_t)tokp[slot] * DIM + k0 + c4 * 4);
      __half* p = sA + r * SH + c4 * 4;
      *(__half2*)(p)     = __floats2half2_rn(val.x, val.y);
      *(__half2*)(p + 2) = __floats2half2_rn(val.z, val.w);
    }
#pragma unroll
    for (int v = 0; v < 2; v++) {
      int i = tid + v * 256;
      int r = i >> 3, c4 = i & 7;
      float4 vg = *(const float4*)(wgp + (size_t)r * DIM + k0 + c4 * 4);
      float4 vu = *(const float4*)(wup + (size_t)r * DIM + k0 + c4 * 4);
      __half* pg = sBg + r * SH + c4 * 4;
      __half* pu = sBu + r * SH + c4 * 4;
      *(__half2*)(pg)     = __floats2half2_rn(vg.x, vg.y);
      *(__half2*)(pg + 2) = __floats2half2_rn(vg.z, vg.w);
      *(__half2*)(pu)     = __floats2half2_rn(vu.x, vu.y);
      *(__half2*)(pu + 2) = __floats2half2_rn(vu.z, vu.w);
    }
    __syncthreads();

#pragma unroll
    for (int kk = 0; kk < 32; kk += 16) {
      wmma::fragment<wmma::matrix_a, 16, 16, 16, __half, wmma::row_major> fa[2];
      wmma::fragment<wmma::matrix_b, 16, 16, 16, __half, wmma::col_major> fbg[2], fbu[2];
#pragma unroll
      for (int i = 0; i < 2; i++)
        wmma::load_matrix_sync(fa[i], sA + (wm + 16 * i) * SH + kk, SH);
#pragma unroll
      for (int j = 0; j < 2; j++) {
        wmma::load_matrix_sync(fbg[j], sBg + (wn + 16 * j) * SH + kk, SH);
        wmma::load_matrix_sync(fbu[j], sBu + (wn + 16 * j) * SH + kk, SH);
      }
#pragma unroll
      for (int i = 0; i < 2; i++)
#pragma unroll
        for (int j = 0; j < 2; j++) {
          wmma::mma_sync(accg[i][j], fa[i], fbg[j], accg[i][j]);
          wmma::mma_sync(accu[i][j], fa[i], fbu[j], accu[i][j]);
        }
    }
    __syncthreads();
  }

  // Epilogue: h = silu(g)*u in registers -> fp32 smem tile -> fp16 gmem
#pragma unroll
  for (int i = 0; i < 2; i++)
#pragma unroll
    for (int j = 0; j < 2; j++) {
#pragma unroll
      for (int q = 0; q < accg[i][j].num_elements; q++) {
        float g = accg[i][j].x[q];
        float u = accu[i][j].x[q];
        accg[i][j].x[q] = g * u / (1.f + __expf(-g));
      }
      wmma::store_matrix_sync(fbuf + (wm + 16 * i) * SF + (wn + 16 * j),
                              accg[i][j], SF, wmma::mem_row_major);
    }
  __syncthreads();

  __half* hp = g_h + (size_t)(g_off[e] + m0) * FFN + n0;
#pragma unroll
  for (int v = 0; v < 16; v++) {        // 128*32 half2 tasks
    int i = tid + v * 256;
    int r = i >> 5, c2 = i & 31;
    float2 f = *(float2*)(fbuf + r * SF + c2 * 2);
    *(__half2*)(hp + (size_t)r * FFN + c2 * 2) = __floats2half2_rn(f.x, f.y);
  }
}

// ---------------------------------------------------------------------------
// GEMM 3 (fp16 WMMA): y = h Wo^T, out[token] += route_w * y (atomic scatter).
// A = g_h (fp16, compacted). K = FFN.
// ---------------------------------------------------------------------------
__global__ void __launch_bounds__(256) k_down(float* __restrict__ out,
                                              const float* __restrict__ wo) {
  const int e  = blockIdx.z;
  const int Te = g_cnt[e];
  const int m0 = blockIdx.x * 128;
  if (m0 >= Te) return;
  const int n0 = blockIdx.y * 64;

  __shared__ __align__(32) char smem[32768];
  __half* sA = (__half*)smem;              // 128*48 halves = 12288 B
  __half* sB = (__half*)(smem + 12288);    // 64*48 = 6144 B
  float*  fbuf = (float*)smem;             // epilogue 32768 B

  const int tid = threadIdx.x;
  const int wid = tid >> 5;
  const int wm = (wid >> 1) * 32;
  const int wn = (wid & 1) * 32;

  wmma::fragment<wmma::accumulator, 16, 16, 16, float> acc[2][2];
#pragma unroll
  for (int i = 0; i < 2; i++)
#pragma unroll
    for (int j = 0; j < 2; j++) wmma::fill_fragment(acc[i][j], 0.f);

  const __half* hp  = g_h + (size_t)(g_off[e] + m0) * FFN;
  const float*  wop = wo + (size_t)e * DIM * FFN + (size_t)n0 * FFN;

  for (int k0 = 0; k0 < FFN; k0 += 32) {
    // sA: fp16 copy, 128 rows x 8 uint2-groups (4 halves each)
#pragma unroll
    for (int v = 0; v < 4; v++) {
      int i = tid + v * 256;
      int r = i >> 3, c4 = i & 7;
      *(uint2*)(sA + r * SH + c4 * 4) =
          *(const uint2*)(hp + (size_t)r * FFN + k0 + c4 * 4);
    }
    // sB: fp32 weights -> fp16
#pragma unroll
    for (int v = 0; v < 2; v++) {
      int i = tid + v * 256;
      int r = i >> 3, c4 = i & 7;
      float4 val = *(const float4*)(wop + (size_t)r * FFN + k0 + c4 * 4);
      __half* p = sB + r * SH + c4 * 4;
      *(__half2*)(p)     = __floats2half2_rn(val.x, val.y);
      *(__half2*)(p + 2) = __floats2half2_rn(val.z, val.w);
    }
    __syncthreads();

#pragma unroll
    for (int kk = 0; kk < 32; kk += 16) {
      wmma::fragment<wmma::matrix_a, 16, 16, 16, __half, wmma::row_major> fa[2];
      wmma::fragment<wmma::matrix_b, 16, 16, 16, __half, wmma::col_major> fb[2];
#pragma unroll
      for (int i = 0; i < 2; i++)
        wmma::load_matrix_sync(fa[i], sA + (wm + 16 * i) * SH + kk, SH);
#pragma unroll
      for (int j = 0; j < 2; j++)
        wmma::load_matrix_sync(fb[j], sB + (wn + 16 * j) * SH + kk, SH);
#pragma unroll
      for (int i = 0; i < 2; i++)
#pragma unroll
        for (int j = 0; j < 2; j++)
          wmma::mma_sync(acc[i][j], fa[i], fb[j], acc[i][j]);
    }
    __syncthreads();
  }

  // Epilogue: fp32 smem staging, then weighted atomic scatter into out
#pragma unroll
  for (int i = 0; i < 2; i++)
#pragma unroll
    for (int j = 0; j < 2; j++)
      wmma::store_matrix_sync(fbuf + (wm + 16 * i) * SF + (wn + 16 * j),
                              acc[i][j], SF, wmma::mem_row_major);
  __syncthreads();

#pragma unroll
  for (int v = 0; v < 32; v++) {
    int i = tid + v * 256;
    int r = i >> 6, c = i & 63;
    int slot = m0 + r;
    if (slot < Te) {
      int   t = g_tok[e * CAP + slot];
      float w = g_wt[e * CAP + slot];
      atomicAdd(&out[(size_t)t * DIM + n0 + c], w * fbuf[r * SF + c]);
    }
  }
}

extern "C" void kernel_launch(void* const* d_in, const int* in_sizes, int n_in,
                              void* d_out, int out_size) {
  const float* x    = (const float*)d_in[0];  // [2,2048,2048]
  const float* gw   = (const float*)d_in[1];  // [8,2048]
  const float* wg   = (const float*)d_in[2];  // [8,5632,2048]
  const float* wu   = (const float*)d_in[3];  // [8,5632,2048]
  const float* wo   = (const float*)d_in[4];  // [8,2048,5632]
  const float* bias = (const float*)d_in[5];  // [2048]
  float* out = (float*)d_out;                 // [2,2048,2048] f32

  k_zero<<<1, 32>>>();
  k_router<<<NTOK / 8, 256>>>(x, gw);
  k_offsets<<<1, 32>>>();
  k_bias<<<(NTOK * DIM + 255) / 256, 256>>>(out, bias);

  dim3 g3(NTOK / 128, FFN / 64, NE);
  k_gateup<<<g3, 256>>>(x, wg, wu);

  dim3 g4(NTOK / 128, DIM / 64, NE);
  k_down<<<g4, 256>>>(out, wo);
}